// round 2
// baseline (speedup 1.0000x reference)
#include <cuda_runtime.h>
#include <math.h>

#define BB 16
#define AA 1024
#define TT 512
#define DD 256
#define TWOD 512
#define NROWS_A (BB*AA)            /* 16384 article rows  */
#define NROWS_T (BB*TT)            /* 8192 template rows  */
#define NROWS   (NROWS_A+NROWS_T)  /* 24576 total rows    */

// Scratch (static device arrays — no runtime allocation)
__device__ float g_buf0[(size_t)NROWS * DD];
__device__ float g_buf1[(size_t)NROWS * DD];
__device__ float g_sq[NROWS];
__device__ float g_rowmax[NROWS_A];

// ---------------------------------------------------------------------------
// Embedding gather: rows [0,16384) = article, [16384,24576) = template
// ---------------------------------------------------------------------------
__global__ void embed_kernel(const int* __restrict__ aw, const int* __restrict__ tw,
                             const float* __restrict__ emb) {
    int gi  = blockIdx.x * blockDim.x + threadIdx.x;   // float4 index
    int row = gi >> 6;
    int c4  = gi & 63;
    int word = (row < NROWS_A) ? aw[row] : tw[row - NROWS_A];
    ((float4*)g_buf0)[row * 64 + c4] = ((const float4*)emb)[word * 64 + c4];
}

// ---------------------------------------------------------------------------
// Fused res-block: y = conv1d_dilated(x)+b; a,g = split(y); out = x + a*sigmoid(g)
// Implicit GEMM, tile 128(L) x 64(channel pairs), per-thread 8x4x2 accumulators.
// x chunk stored transposed so row operands load as LDS.128.
// grid.x: 192 row tiles (128 article + 64 template), grid.y: 4 channel groups.
// ---------------------------------------------------------------------------
__global__ __launch_bounds__(256, 2) void conv_glu_kernel(
    const float* __restrict__ xin, float* __restrict__ xout,
    const float* __restrict__ w, const float* __restrict__ bias, int dil)
{
    const int t = blockIdx.x, cg = blockIdx.y;
    int base, l0, L;
    if (t < 128) { int s = t >> 3;       l0 = (t & 7) << 7;        base = s * AA;            L = AA; }
    else         { int s = (t - 128) >> 2; l0 = ((t - 128) & 3) << 7; base = NROWS_A + s * TT; L = TT; }

    const int tid = threadIdx.x;
    const int tx = tid & 15;          // column group (4 cols)
    const int ty = tid >> 4;          // row group (8 rows)
    const int cb = cg << 6;           // channel-pair base

    __shared__ __align__(16) float xs[32][132];   // transposed x: xs[d][l]
    __shared__ __align__(16) float wa[32][68];    // weights 'a' half
    __shared__ __align__(16) float wg[32][68];    // weights 'g' half

    float acc_a[8][4] = {};
    float acc_g[8][4] = {};

    for (int k = 0; k < 3; ++k) {
        const int off = (k - 1) * dil;
        for (int dc = 0; dc < DD; dc += 32) {
            // load x chunk transposed (zero-padded at sequence boundary)
            #pragma unroll
            for (int s = 0; s < 16; ++s) {
                int idx = tid + s * 256;
                int d = idx & 31, l = idx >> 5;
                int lg = l0 + l + off;
                float v = 0.f;
                if (lg >= 0 && lg < L) v = xin[(size_t)(base + lg) * DD + dc + d];
                xs[d][l] = v;
            }
            // load weight chunk for both GLU halves
            #pragma unroll
            for (int s = 0; s < 2; ++s) {
                int fi = tid + s * 256;
                int r = fi >> 4, c4 = (fi & 15) << 2;
                const float* wr = w + (size_t)(k * DD + dc + r) * TWOD + cb + c4;
                *(float4*)&wa[r][c4] = *(const float4*)wr;
                *(float4*)&wg[r][c4] = *(const float4*)(wr + DD);
            }
            __syncthreads();

            #pragma unroll 4
            for (int dd = 0; dd < 32; ++dd) {
                float4 x0 = *(const float4*)&xs[dd][ty * 8];
                float4 x1 = *(const float4*)&xs[dd][ty * 8 + 4];
                float4 a4 = *(const float4*)&wa[dd][tx * 4];
                float4 g4 = *(const float4*)&wg[dd][tx * 4];
                float xr[8] = {x0.x, x0.y, x0.z, x0.w, x1.x, x1.y, x1.z, x1.w};
                float av[4] = {a4.x, a4.y, a4.z, a4.w};
                float gv[4] = {g4.x, g4.y, g4.z, g4.w};
                #pragma unroll
                for (int i = 0; i < 8; ++i)
                    #pragma unroll
                    for (int j = 0; j < 4; ++j) {
                        acc_a[i][j] = fmaf(xr[i], av[j], acc_a[i][j]);
                        acc_g[i][j] = fmaf(xr[i], gv[j], acc_g[i][j]);
                    }
            }
            __syncthreads();
        }
    }

    float4 ba4 = *(const float4*)&bias[cb + tx * 4];
    float4 bg4 = *(const float4*)&bias[DD + cb + tx * 4];
    const float ba[4] = {ba4.x, ba4.y, ba4.z, ba4.w};
    const float bg[4] = {bg4.x, bg4.y, bg4.z, bg4.w};

    #pragma unroll
    for (int i = 0; i < 8; ++i) {
        int gr = base + l0 + ty * 8 + i;
        const float4 rx = *(const float4*)&xin[(size_t)gr * DD + cb + tx * 4];
        float r[4] = {rx.x, rx.y, rx.z, rx.w};
        float ov[4];
        #pragma unroll
        for (int j = 0; j < 4; ++j) {
            float a = acc_a[i][j] + ba[j];
            float g = acc_g[i][j] + bg[j];
            float sg = 1.f / (1.f + expf(-g));
            ov[j] = r[j] + a * sg;
        }
        float4 o; o.x = ov[0]; o.y = ov[1]; o.z = ov[2]; o.w = ov[3];
        *(float4*)&xout[(size_t)gr * DD + cb + tx * 4] = o;
    }
}

// ---------------------------------------------------------------------------
// Per-row squared norm of final encodings
// ---------------------------------------------------------------------------
__global__ void sqnorm_kernel(const float* __restrict__ x) {
    int row = blockIdx.x;
    int lane = threadIdx.x;  // 32 threads
    const float4* r4 = (const float4*)(x + (size_t)row * DD);
    float s = 0.f;
    #pragma unroll
    for (int i = 0; i < 2; ++i) {
        float4 v = r4[lane + i * 32];
        s += v.x*v.x + v.y*v.y + v.z*v.z + v.w*v.w;
    }
    #pragma unroll
    for (int o = 16; o; o >>= 1) s += __shfl_xor_sync(0xffffffffu, s, o);
    if (lane == 0) g_sq[row] = s;
}

// ---------------------------------------------------------------------------
// Fused: dot = art·tplT per batch, dist, S = exp(-dist)*am*tm, rowmax over T.
// grid (16 a-tiles, 16 batches); block computes 64 art rows vs all 512 tpl.
// ---------------------------------------------------------------------------
__global__ __launch_bounds__(256) void dist_rowmax_kernel(
    const float* __restrict__ x, const float* __restrict__ am, const float* __restrict__ tm)
{
    const int b = blockIdx.y;
    const int a0 = blockIdx.x << 6;
    const int tid = threadIdx.x, tx = tid & 15, ty = tid >> 4;

    __shared__ float arts[64][33];
    __shared__ float tps[64][33];
    __shared__ float a2s[64], ams[64], t2s[64], tms[64];
    __shared__ float red[64][17];

    const int abase = b * AA + a0;          // global row index (article region)
    const int tbase = NROWS_A + b * TT;     // global row index (template region)

    if (tid < 64) {
        a2s[tid] = g_sq[abase + tid];
        ams[tid] = am[b * AA + a0 + tid];
    }
    float lm[4] = {0.f, 0.f, 0.f, 0.f};     // S >= 0, so 0 is a valid identity

    for (int t0 = 0; t0 < TT; t0 += 64) {
        if (tid < 64) {
            t2s[tid] = g_sq[tbase + t0 + tid];
            tms[tid] = tm[b * TT + t0 + tid];
        }
        float acc[4][4] = {};
        for (int dc = 0; dc < DD; dc += 32) {
            #pragma unroll
            for (int s = 0; s < 8; ++s) {
                int e = tid + s * 256;
                int l = e >> 5, c = e & 31;
                arts[l][c] = x[(size_t)(abase + l) * DD + dc + c];
                tps[l][c]  = x[(size_t)(tbase + t0 + l) * DD + dc + c];
            }
            __syncthreads();
            #pragma unroll
            for (int dd = 0; dd < 32; ++dd) {
                float ar[4], tr[4];
                #pragma unroll
                for (int i = 0; i < 4; ++i) ar[i] = arts[ty * 4 + i][dd];
                #pragma unroll
                for (int j = 0; j < 4; ++j) tr[j] = tps[tx * 4 + j][dd];
                #pragma unroll
                for (int i = 0; i < 4; ++i)
                    #pragma unroll
                    for (int j = 0; j < 4; ++j)
                        acc[i][j] = fmaf(ar[i], tr[j], acc[i][j]);
            }
            __syncthreads();
        }
        #pragma unroll
        for (int i = 0; i < 4; ++i) {
            int r = ty * 4 + i;
            #pragma unroll
            for (int j = 0; j < 4; ++j) {
                int tj = tx * 4 + j;
                float dist = a2s[r] + t2s[tj] - 2.f * acc[i][j];
                dist = fmaxf(dist, 0.f);
                float S = expf(-dist) * ams[r] * tms[tj];
                lm[i] = fmaxf(lm[i], S);
            }
        }
        __syncthreads();  // protect t2s/tms before next chunk overwrites
    }

    #pragma unroll
    for (int i = 0; i < 4; ++i) red[ty * 4 + i][tx] = lm[i];
    __syncthreads();
    if (tid < 64) {
        float m = red[tid][0];
        #pragma unroll
        for (int xx = 1; xx < 16; ++xx) m = fmaxf(m, red[tid][xx]);
        g_rowmax[b * AA + a0 + tid] = m;
    }
}

// ---------------------------------------------------------------------------
// Top-10 (sorted desc) + tiny 2-layer MLP -> out[b]
// ---------------------------------------------------------------------------
__global__ __launch_bounds__(256) void topk_ff_kernel(
    const float* __restrict__ f1w, const float* __restrict__ f1b,
    const float* __restrict__ f2w, const float* __restrict__ f2b,
    float* __restrict__ out)
{
    const int b = blockIdx.x;
    const int tid = threadIdx.x;
    __shared__ float vals[AA];
    __shared__ float sv[256];
    __shared__ int   si[256];
    __shared__ float top[10];

    #pragma unroll
    for (int s = 0; s < 4; ++s) vals[tid + s * 256] = g_rowmax[b * AA + tid + s * 256];
    __syncthreads();

    for (int it = 0; it < 10; ++it) {
        float v = -1.f; int idx = 1 << 20;
        #pragma unroll
        for (int s = 0; s < 4; ++s) {
            int i = s * 256 + tid;
            float xv = vals[i];
            if (xv > v || (xv == v && i < idx)) { v = xv; idx = i; }
        }
        sv[tid] = v; si[tid] = idx;
        __syncthreads();
        for (int o = 128; o; o >>= 1) {
            if (tid < o) {
                if (sv[tid+o] > sv[tid] || (sv[tid+o] == sv[tid] && si[tid+o] < si[tid])) {
                    sv[tid] = sv[tid+o]; si[tid] = si[tid+o];
                }
            }
            __syncthreads();
        }
        if (tid == 0) { top[it] = sv[0]; vals[si[0]] = -1.f; }
        __syncthreads();
    }

    if (tid == 0) {
        float o = f2b[0];
        #pragma unroll
        for (int j = 0; j < 10; ++j) {
            float h = f1b[j];
            #pragma unroll
            for (int i = 0; i < 10; ++i) h += top[i] * f1w[i * 10 + j];
            h = fmaxf(h, 0.f);
            o += h * f2w[j];
        }
        out[b] = o;
    }
}

// ---------------------------------------------------------------------------
// Launch
// ---------------------------------------------------------------------------
extern "C" void kernel_launch(void* const* d_in, const int* in_sizes, int n_in,
                              void* d_out, int out_size) {
    const int*   aw    = (const int*)d_in[0];
    const int*   tw    = (const int*)d_in[2];
    const float* am    = (const float*)d_in[4];
    const float* tm    = (const float*)d_in[5];
    const float* emb   = (const float*)d_in[6];
    const float* exp_w = (const float*)d_in[7];
    const float* exp_b = (const float*)d_in[8];
    const float* ref_w = (const float*)d_in[9];
    const float* ref_b = (const float*)d_in[10];
    const float* f1w   = (const float*)d_in[11];
    const float* f1b   = (const float*)d_in[12];
    const float* f2w   = (const float*)d_in[13];
    const float* f2b   = (const float*)d_in[14];
    float* out = (float*)d_out;

    float *b0 = nullptr, *b1 = nullptr;
    cudaGetSymbolAddress((void**)&b0, g_buf0);
    cudaGetSymbolAddress((void**)&b1, g_buf1);

    embed_kernel<<<(NROWS * 64) / 256, 256>>>(aw, tw, emb);

    const int dils[10] = {1, 2, 4, 8, 16, 32, 32, 1, 1, 1};
    float* src = b0;
    float* dst = b1;
    for (int i = 0; i < 10; ++i) {
        const float* w  = (i < 7) ? exp_w + (size_t)i * 3 * DD * TWOD
                                  : ref_w + (size_t)(i - 7) * 3 * DD * TWOD;
        const float* bs = (i < 7) ? exp_b + i * TWOD : ref_b + (i - 7) * TWOD;
        conv_glu_kernel<<<dim3(192, 4), 256>>>(src, dst, w, bs, dils[i]);
        float* tmp = src; src = dst; dst = tmp;
    }
    // 10 swaps (even) -> final encodings are back in b0 == src
    sqnorm_kernel<<<NROWS, 32>>>(src);
    dist_rowmax_kernel<<<dim3(16, 16), 256>>>(src, am, tm);
    topk_ff_kernel<<<16, 256>>>(f1w, f1b, f2w, f2b, out);
}

// round 5
// speedup vs baseline: 1.9198x; 1.9198x over previous
#include <cuda_runtime.h>
#include <cuda_bf16.h>
#include <math.h>
#include <stdint.h>

#define BB 16
#define AA 1024
#define TT 512
#define DD 256
#define TWOD 512
#define KTOT 768                     /* 3 taps * 256 channels */
#define NROWS_A (BB*AA)              /* 16384 */
#define NROWS_T (BB*TT)              /* 8192  */
#define NROWS   (NROWS_A+NROWS_T)    /* 24576 */
#define NLAYER 10

// ---------------- static device scratch (no runtime allocation) ----------------
__device__ float g_buf0[(size_t)NROWS * DD];
__device__ float g_buf1[(size_t)NROWS * DD];
__device__ __nv_bfloat16 g_xh[(size_t)NROWS * DD];
__device__ __nv_bfloat16 g_xl[(size_t)NROWS * DD];
__device__ __nv_bfloat16 g_wt_hi[(size_t)NLAYER * TWOD * KTOT];
__device__ __nv_bfloat16 g_wt_lo[(size_t)NLAYER * TWOD * KTOT];
__device__ float g_sq[NROWS];
__device__ float g_rowmax[NROWS_A];

// ---------------- helpers ----------------
__device__ __forceinline__ uint32_t smem_u32(const void* p) {
    uint32_t a;
    asm("{ .reg .u64 t; cvta.to.shared.u64 t, %1; cvt.u32.u64 %0, t; }" : "=r"(a) : "l"(p));
    return a;
}
__device__ __forceinline__ void cpa16(uint32_t dst, const void* src, uint32_t sz) {
    asm volatile("cp.async.ca.shared.global [%0], [%1], 16, %2;"
                 :: "r"(dst), "l"(src), "r"(sz) : "memory");
}
#define CP_COMMIT() asm volatile("cp.async.commit_group;" ::: "memory")
#define CP_WAIT1()  asm volatile("cp.async.wait_group 1;" ::: "memory")
#define CP_WAIT0()  asm volatile("cp.async.wait_group 0;" ::: "memory")

#define MMA_BF16(dd, a, b0, b1)                                              \
    asm volatile("mma.sync.aligned.m16n8k16.row.col.f32.bf16.bf16.f32 "      \
        "{%0,%1,%2,%3}, {%4,%5,%6,%7}, {%8,%9}, {%0,%1,%2,%3};"              \
        : "+f"((dd)[0]), "+f"((dd)[1]), "+f"((dd)[2]), "+f"((dd)[3])         \
        : "r"((a)[0]), "r"((a)[1]), "r"((a)[2]), "r"((a)[3]), "r"(b0), "r"(b1))

// smem stage layout (bytes), padded row stride 80B (=40 bf16) -> conflict-free
#define A_HI 0
#define A_LO 10240
#define B_HI 20480
#define B_LO 30720
#define STAGE_BYTES 40960
#define CONV_SMEM (2 * STAGE_BYTES)

// ---------------------------------------------------------------------------
// Embedding gather
// ---------------------------------------------------------------------------
__global__ void embed_kernel(const int* __restrict__ aw, const int* __restrict__ tw,
                             const float* __restrict__ emb) {
    int gi  = blockIdx.x * blockDim.x + threadIdx.x;
    int row = gi >> 6;
    int c4  = gi & 63;
    int word = (row < NROWS_A) ? aw[row] : tw[row - NROWS_A];
    ((float4*)g_buf0)[row * 64 + c4] = ((const float4*)emb)[word * 64 + c4];
}

// ---------------------------------------------------------------------------
// Weight prep: w[(tap*256+d)*512 + n] -> wt[bn][tap*256+d], hi/lo bf16 split.
// bn interleaves GLU partners: bn = 2*(n&255) + (n>>8)  (a at even, g at odd)
// grid (24, 16, 10), block (32, 8)
// ---------------------------------------------------------------------------
__global__ void wprep_kernel(const float* __restrict__ exp_w, const float* __restrict__ ref_w) {
    int layer = blockIdx.z;
    const float* w = (layer < 7) ? exp_w + (size_t)layer * KTOT * TWOD
                                 : ref_w + (size_t)(layer - 7) * KTOT * TWOD;
    __shared__ float tile[32][33];
    int kk0 = blockIdx.x * 32, n0 = blockIdx.y * 32;
    int tx = threadIdx.x, ty = threadIdx.y;
    #pragma unroll
    for (int j = 0; j < 4; ++j)
        tile[ty + j * 8][tx] = w[(size_t)(kk0 + ty + j * 8) * TWOD + n0 + tx];
    __syncthreads();
    #pragma unroll
    for (int j = 0; j < 4; ++j) {
        int n = n0 + ty + j * 8, kk = kk0 + tx;
        float v = tile[tx][ty + j * 8];
        __nv_bfloat16 h = __float2bfloat16(v);
        __nv_bfloat16 l = __float2bfloat16(v - __bfloat162float(h));
        int bn = 2 * (n & 255) + (n >> 8);
        size_t o = (size_t)layer * TWOD * KTOT + (size_t)bn * KTOT + kk;
        g_wt_hi[o] = h; g_wt_lo[o] = l;
    }
}

// ---------------------------------------------------------------------------
// Activation split: fp32 -> bf16 hi + bf16 lo (8 elems / thread)
// ---------------------------------------------------------------------------
__global__ void xprep_kernel(const float* __restrict__ x) {
    int gi = blockIdx.x * blockDim.x + threadIdx.x;       // 16B group index
    const float4* s = (const float4*)x + (size_t)gi * 2;
    float4 v0 = s[0], v1 = s[1];
    float f[8] = {v0.x, v0.y, v0.z, v0.w, v1.x, v1.y, v1.z, v1.w};
    uint32_t hp[4], lp[4];
    #pragma unroll
    for (int j = 0; j < 4; ++j) {
        __nv_bfloat162 h2 = __floats2bfloat162_rn(f[2*j], f[2*j+1]);
        float r0 = f[2*j]   - __low2float(h2);
        float r1 = f[2*j+1] - __high2float(h2);
        __nv_bfloat162 l2 = __floats2bfloat162_rn(r0, r1);
        hp[j] = *reinterpret_cast<uint32_t*>(&h2);
        lp[j] = *reinterpret_cast<uint32_t*>(&l2);
    }
    ((uint4*)g_xh)[gi] = make_uint4(hp[0], hp[1], hp[2], hp[3]);
    ((uint4*)g_xl)[gi] = make_uint4(lp[0], lp[1], lp[2], lp[3]);
}

// ---------------------------------------------------------------------------
// bf16 mma.sync conv+GLU res-block.
// Block tile M=128 x N=128 (64 GLU pairs interleaved a,g) x K=768 (chunks of 32).
// 8 warps as 2(M) x 4(N); warp tile 64x32; 3-term hi/lo; cp.async double buffer.
// grid (192 row tiles, 4 pair groups), 256 threads.
// ---------------------------------------------------------------------------
__global__ __launch_bounds__(256) void conv_mma_kernel(
    const __nv_bfloat16* __restrict__ xh, const __nv_bfloat16* __restrict__ xl,
    const float* __restrict__ xin, float* __restrict__ xout,
    const __nv_bfloat16* __restrict__ wh, const __nv_bfloat16* __restrict__ wl,
    const float* __restrict__ bias, int dil)
{
    extern __shared__ char dsm[];
    const uint32_t smb = smem_u32(dsm);
    const int tid = threadIdx.x;
    const int lane = tid & 31, wid = tid >> 5;
    const int wm = wid & 1, wn = wid >> 1;       // 2 x 4 warp grid
    const int cg = blockIdx.y;                   // 64 GLU pairs per group

    const int t = blockIdx.x;
    int base, l0, L;
    if (t < 128) { int s = t >> 3;         l0 = (t & 7) << 7;         base = s * AA;           L = AA; }
    else         { int s = (t - 128) >> 2; l0 = ((t - 128) & 3) << 7; base = NROWS_A + s * TT; L = TT; }

    const int lr  = tid >> 2;       // 0..63 loader row
    const int seg = tid & 3;        // 16B segment

    float d[4][4][4];
    #pragma unroll
    for (int i = 0; i < 4; ++i)
        #pragma unroll
        for (int j = 0; j < 4; ++j)
            #pragma unroll
            for (int u = 0; u < 4; ++u) d[i][j][u] = 0.f;

    // ---- chunk loader ----
    auto load_chunk = [&](int ci, int stage) {
        const int tap = ci >> 3;
        const int dc  = (ci & 7) * 32;
        const int off = (tap - 1) * dil;
        const uint32_t st = smb + stage * STAGE_BYTES;
        const int kk = tap * 256 + dc;
        #pragma unroll
        for (int i = 0; i < 2; ++i) {
            int r = lr + i * 64;
            // A (shifted activations, zero-filled out of range)
            int ll = l0 + r + off;
            uint32_t sz = (ll >= 0 && ll < L) ? 16u : 0u;
            int grow = base + (sz ? ll : 0);
            const char* sa_h = (const char*)(xh + (size_t)grow * DD + dc) + seg * 16;
            const char* sa_l = (const char*)(xl + (size_t)grow * DD + dc) + seg * 16;
            uint32_t da = st + A_HI + r * 80 + seg * 16;
            cpa16(da, sa_h, sz);
            cpa16(da + (A_LO - A_HI), sa_l, sz);
            // B (pre-transposed weights)
            const char* sb_h = (const char*)(wh + (size_t)(cg * 128 + r) * KTOT + kk) + seg * 16;
            const char* sb_l = (const char*)(wl + (size_t)(cg * 128 + r) * KTOT + kk) + seg * 16;
            uint32_t db = st + B_HI + r * 80 + seg * 16;
            cpa16(db, sb_h, 16u);
            cpa16(db + (B_LO - B_HI), sb_l, 16u);
        }
    };

    load_chunk(0, 0);
    CP_COMMIT();

    for (int ci = 0; ci < 24; ++ci) {
        if (ci < 23) { load_chunk(ci + 1, (ci + 1) & 1); CP_COMMIT(); CP_WAIT1(); }
        else         { CP_WAIT0(); }
        __syncthreads();

        const char* st = dsm + (ci & 1) * STAGE_BYTES;
        #pragma unroll
        for (int ks = 0; ks < 2; ++ks) {
            const int k0b = (ks * 16 + (lane & 3) * 2) * 2;   // byte offset of k
            uint32_t ahi[4][4], alo[4][4];
            #pragma unroll
            for (int mt = 0; mt < 4; ++mt) {
                int r = wm * 64 + mt * 16 + (lane >> 2);
                const char* pa = st + r * 80 + k0b;
                ahi[mt][0] = *(const uint32_t*)(pa + A_HI);
                ahi[mt][1] = *(const uint32_t*)(pa + A_HI + 8 * 80);
                ahi[mt][2] = *(const uint32_t*)(pa + A_HI + 16);
                ahi[mt][3] = *(const uint32_t*)(pa + A_HI + 8 * 80 + 16);
                alo[mt][0] = *(const uint32_t*)(pa + A_LO);
                alo[mt][1] = *(const uint32_t*)(pa + A_LO + 8 * 80);
                alo[mt][2] = *(const uint32_t*)(pa + A_LO + 16);
                alo[mt][3] = *(const uint32_t*)(pa + A_LO + 8 * 80 + 16);
            }
            #pragma unroll
            for (int nt = 0; nt < 4; ++nt) {
                int n = wn * 32 + nt * 8 + (lane >> 2);
                const char* pb = st + n * 80 + k0b;
                uint32_t bh0 = *(const uint32_t*)(pb + B_HI);
                uint32_t bh1 = *(const uint32_t*)(pb + B_HI + 16);
                uint32_t bl0 = *(const uint32_t*)(pb + B_LO);
                uint32_t bl1 = *(const uint32_t*)(pb + B_LO + 16);
                #pragma unroll
                for (int mt = 0; mt < 4; ++mt) {
                    MMA_BF16(d[mt][nt], ahi[mt], bh0, bh1);
                    MMA_BF16(d[mt][nt], alo[mt], bh0, bh1);
                    MMA_BF16(d[mt][nt], ahi[mt], bl0, bl1);
                }
            }
        }
        __syncthreads();
    }

    // ---- epilogue: GLU + residual.  c0=a,c1=g (rows r), c2=a,c3=g (rows r+8) ----
    #pragma unroll
    for (int nt = 0; nt < 4; ++nt) {
        const int p  = cg * 64 + wn * 16 + nt * 4 + (lane & 3);
        const float ba = bias[p], bg = bias[DD + p];
        #pragma unroll
        for (int mt = 0; mt < 4; ++mt) {
            const int r0 = base + l0 + wm * 64 + mt * 16 + (lane >> 2);
            {
                float a = d[mt][nt][0] + ba;
                float g = d[mt][nt][1] + bg;
                xout[(size_t)r0 * DD + p] = xin[(size_t)r0 * DD + p] + a * (1.f / (1.f + expf(-g)));
            }
            {
                float a = d[mt][nt][2] + ba;
                float g = d[mt][nt][3] + bg;
                xout[(size_t)(r0 + 8) * DD + p] = xin[(size_t)(r0 + 8) * DD + p] + a * (1.f / (1.f + expf(-g)));
            }
        }
    }
}

// ---------------------------------------------------------------------------
// Per-row squared norm
// ---------------------------------------------------------------------------
__global__ void sqnorm_kernel(const float* __restrict__ x) {
    int row = blockIdx.x;
    int lane = threadIdx.x;
    const float4* r4 = (const float4*)(x + (size_t)row * DD);
    float s = 0.f;
    #pragma unroll
    for (int i = 0; i < 2; ++i) {
        float4 v = r4[lane + i * 32];
        s += v.x*v.x + v.y*v.y + v.z*v.z + v.w*v.w;
    }
    #pragma unroll
    for (int o = 16; o; o >>= 1) s += __shfl_xor_sync(0xffffffffu, s, o);
    if (lane == 0) g_sq[row] = s;
}

// ---------------------------------------------------------------------------
// Fused dist -> S -> rowmax
// ---------------------------------------------------------------------------
__global__ __launch_bounds__(256) void dist_rowmax_kernel(
    const float* __restrict__ x, const float* __restrict__ am, const float* __restrict__ tm)
{
    const int b = blockIdx.y;
    const int a0 = blockIdx.x << 6;
    const int tid = threadIdx.x, tx = tid & 15, ty = tid >> 4;

    __shared__ float arts[64][33];
    __shared__ float tps[64][33];
    __shared__ float a2s[64], ams[64], t2s[64], tms[64];
    __shared__ float red[64][17];

    const int abase = b * AA + a0;
    const int tbase = NROWS_A + b * TT;

    if (tid < 64) {
        a2s[tid] = g_sq[abase + tid];
        ams[tid] = am[b * AA + a0 + tid];
    }
    float lm[4] = {0.f, 0.f, 0.f, 0.f};

    for (int t0 = 0; t0 < TT; t0 += 64) {
        if (tid < 64) {
            t2s[tid] = g_sq[tbase + t0 + tid];
            tms[tid] = tm[b * TT + t0 + tid];
        }
        float acc[4][4] = {};
        for (int dc = 0; dc < DD; dc += 32) {
            #pragma unroll
            for (int s = 0; s < 8; ++s) {
                int e = tid + s * 256;
                int l = e >> 5, c = e & 31;
                arts[l][c] = x[(size_t)(abase + l) * DD + dc + c];
                tps[l][c]  = x[(size_t)(tbase + t0 + l) * DD + dc + c];
            }
            __syncthreads();
            #pragma unroll
            for (int dd = 0; dd < 32; ++dd) {
                float ar[4], tr[4];
                #pragma unroll
                for (int i = 0; i < 4; ++i) ar[i] = arts[ty * 4 + i][dd];
                #pragma unroll
                for (int j = 0; j < 4; ++j) tr[j] = tps[tx * 4 + j][dd];
                #pragma unroll
                for (int i = 0; i < 4; ++i)
                    #pragma unroll
                    for (int j = 0; j < 4; ++j)
                        acc[i][j] = fmaf(ar[i], tr[j], acc[i][j]);
            }
            __syncthreads();
        }
        #pragma unroll
        for (int i = 0; i < 4; ++i) {
            int r = ty * 4 + i;
            #pragma unroll
            for (int j = 0; j < 4; ++j) {
                int tj = tx * 4 + j;
                float dist = a2s[r] + t2s[tj] - 2.f * acc[i][j];
                dist = fmaxf(dist, 0.f);
                float S = expf(-dist) * ams[r] * tms[tj];
                lm[i] = fmaxf(lm[i], S);
            }
        }
        __syncthreads();
    }

    #pragma unroll
    for (int i = 0; i < 4; ++i) red[ty * 4 + i][tx] = lm[i];
    __syncthreads();
    if (tid < 64) {
        float m = red[tid][0];
        #pragma unroll
        for (int xx = 1; xx < 16; ++xx) m = fmaxf(m, red[tid][xx]);
        g_rowmax[b * AA + a0 + tid] = m;
    }
}

// ---------------------------------------------------------------------------
// Top-10 + tiny MLP
// ---------------------------------------------------------------------------
__global__ __launch_bounds__(256) void topk_ff_kernel(
    const float* __restrict__ f1w, const float* __restrict__ f1b,
    const float* __restrict__ f2w, const float* __restrict__ f2b,
    float* __restrict__ out)
{
    const int b = blockIdx.x;
    const int tid = threadIdx.x;
    __shared__ float vals[AA];
    __shared__ float sv[256];
    __shared__ int   si[256];
    __shared__ float top[10];

    #pragma unroll
    for (int s = 0; s < 4; ++s) vals[tid + s * 256] = g_rowmax[b * AA + tid + s * 256];
    __syncthreads();

    for (int it = 0; it < 10; ++it) {
        float v = -1.f; int idx = 1 << 20;
        #pragma unroll
        for (int s = 0; s < 4; ++s) {
            int i = s * 256 + tid;
            float xv = vals[i];
            if (xv > v || (xv == v && i < idx)) { v = xv; idx = i; }
        }
        sv[tid] = v; si[tid] = idx;
        __syncthreads();
        for (int o = 128; o; o >>= 1) {
            if (tid < o) {
                if (sv[tid+o] > sv[tid] || (sv[tid+o] == sv[tid] && si[tid+o] < si[tid])) {
                    sv[tid] = sv[tid+o]; si[tid] = si[tid+o];
                }
            }
            __syncthreads();
        }
        if (tid == 0) { top[it] = sv[0]; vals[si[0]] = -1.f; }
        __syncthreads();
    }

    if (tid == 0) {
        float o = f2b[0];
        #pragma unroll
        for (int j = 0; j < 10; ++j) {
            float h = f1b[j];
            #pragma unroll
            for (int i = 0; i < 10; ++i) h += top[i] * f1w[i * 10 + j];
            h = fmaxf(h, 0.f);
            o += h * f2w[j];
        }
        out[b] = o;
    }
}

// ---------------------------------------------------------------------------
// Launch
// ---------------------------------------------------------------------------
extern "C" void kernel_launch(void* const* d_in, const int* in_sizes, int n_in,
                              void* d_out, int out_size) {
    const int*   aw    = (const int*)d_in[0];
    const int*   tw    = (const int*)d_in[2];
    const float* am    = (const float*)d_in[4];
    const float* tm    = (const float*)d_in[5];
    const float* emb   = (const float*)d_in[6];
    const float* exp_w = (const float*)d_in[7];
    const float* exp_b = (const float*)d_in[8];
    const float* ref_w = (const float*)d_in[9];
    const float* ref_b = (const float*)d_in[10];
    const float* f1w   = (const float*)d_in[11];
    const float* f1b   = (const float*)d_in[12];
    const float* f2w   = (const float*)d_in[13];
    const float* f2b   = (const float*)d_in[14];
    float* out = (float*)d_out;

    float *b0 = nullptr, *b1 = nullptr;
    __nv_bfloat16 *xh = nullptr, *xl = nullptr, *wh = nullptr, *wl = nullptr;
    cudaGetSymbolAddress((void**)&b0, g_buf0);
    cudaGetSymbolAddress((void**)&b1, g_buf1);
    cudaGetSymbolAddress((void**)&xh, g_xh);
    cudaGetSymbolAddress((void**)&xl, g_xl);
    cudaGetSymbolAddress((void**)&wh, g_wt_hi);
    cudaGetSymbolAddress((void**)&wl, g_wt_lo);

    cudaFuncSetAttribute(conv_mma_kernel, cudaFuncAttributeMaxDynamicSharedMemorySize, CONV_SMEM);

    embed_kernel<<<(NROWS * 64) / 256, 256>>>(aw, tw, emb);
    wprep_kernel<<<dim3(KTOT / 32, TWOD / 32, NLAYER), dim3(32, 8)>>>(exp_w, ref_w);

    const int dils[10] = {1, 2, 4, 8, 16, 32, 32, 1, 1, 1};
    float* src = b0;
    float* dst = b1;
    for (int i = 0; i < 10; ++i) {
        const float* bs = (i < 7) ? exp_b + i * TWOD : ref_b + (i - 7) * TWOD;
        xprep_kernel<<<(NROWS * DD / 8) / 256, 256>>>(src);
        conv_mma_kernel<<<dim3(192, 4), 256, CONV_SMEM>>>(
            xh, xl, src, dst,
            wh + (size_t)i * TWOD * KTOT, wl + (size_t)i * TWOD * KTOT, bs, dils[i]);
        float* tmp = src; src = dst; dst = tmp;
    }
    // 10 swaps (even) -> final encodings in b0 == src
    sqnorm_kernel<<<NROWS, 32>>>(src);
    dist_rowmax_kernel<<<dim3(16, 16), 256>>>(src, am, tm);
    topk_ff_kernel<<<16, 256>>>(f1w, f1b, f2w, f2b, out);
}

// round 10
// speedup vs baseline: 2.3682x; 1.2336x over previous
#include <cuda_runtime.h>
#include <cuda_bf16.h>
#include <math.h>
#include <stdint.h>

#define BB 16
#define AA 1024
#define TT 512
#define DD 256
#define TWOD 512
#define KTOT 768                     /* 3 taps * 256 channels */
#define NROWS_A (BB*AA)              /* 16384 */
#define NROWS_T (BB*TT)              /* 8192  */
#define NROWS   (NROWS_A+NROWS_T)    /* 24576 */
#define NLAYER 10

// ---------------- static device scratch (no runtime allocation) ----------------
__device__ float g_buf0[(size_t)NROWS * DD];
__device__ float g_buf1[(size_t)NROWS * DD];
__device__ __nv_bfloat16 g_xh0[(size_t)NROWS * DD];
__device__ __nv_bfloat16 g_xl0[(size_t)NROWS * DD];
__device__ __nv_bfloat16 g_xh1[(size_t)NROWS * DD];
__device__ __nv_bfloat16 g_xl1[(size_t)NROWS * DD];
__device__ __nv_bfloat16 g_wt_hi[(size_t)NLAYER * TWOD * KTOT];
__device__ __nv_bfloat16 g_wt_lo[(size_t)NLAYER * TWOD * KTOT];
__device__ float g_sq[NROWS];
__device__ float g_rowmax[NROWS_A];

// ---------------- helpers ----------------
__device__ __forceinline__ uint32_t smem_u32(const void* p) {
    uint32_t a;
    asm("{ .reg .u64 t; cvta.to.shared.u64 t, %1; cvt.u32.u64 %0, t; }" : "=r"(a) : "l"(p));
    return a;
}
__device__ __forceinline__ void cpa16(uint32_t dst, const void* src, uint32_t sz) {
    asm volatile("cp.async.ca.shared.global [%0], [%1], 16, %2;"
                 :: "r"(dst), "l"(src), "r"(sz) : "memory");
}
#define CP_COMMIT() asm volatile("cp.async.commit_group;" ::: "memory")
#define CP_WAIT1()  asm volatile("cp.async.wait_group 1;" ::: "memory")
#define CP_WAIT0()  asm volatile("cp.async.wait_group 0;" ::: "memory")

#define MMA_BF16(dd, a, b0, b1)                                              \
    asm volatile("mma.sync.aligned.m16n8k16.row.col.f32.bf16.bf16.f32 "      \
        "{%0,%1,%2,%3}, {%4,%5,%6,%7}, {%8,%9}, {%0,%1,%2,%3};"              \
        : "+f"((dd)[0]), "+f"((dd)[1]), "+f"((dd)[2]), "+f"((dd)[3])         \
        : "r"((a)[0]), "r"((a)[1]), "r"((a)[2]), "r"((a)[3]), "r"(b0), "r"(b1))

#define LDMX4(r, a)                                                          \
    asm volatile("ldmatrix.sync.aligned.m8n8.x4.shared.b16 {%0,%1,%2,%3}, [%4];" \
        : "=r"((r)[0]), "=r"((r)[1]), "=r"((r)[2]), "=r"((r)[3]) : "r"(a))

// smem stage layout (bytes), padded row stride 80B (=40 bf16) -> conflict-free
#define A_HI 0
#define A_LO 10240
#define B_HI 20480
#define B_LO 30720
#define STAGE_BYTES 40960
#define CONV_SMEM (2 * STAGE_BYTES)

// ---------------------------------------------------------------------------
// Embedding gather
// ---------------------------------------------------------------------------
__global__ void embed_kernel(const int* __restrict__ aw, const int* __restrict__ tw,
                             const float* __restrict__ emb) {
    int gi  = blockIdx.x * blockDim.x + threadIdx.x;
    int row = gi >> 6;
    int c4  = gi & 63;
    int word = (row < NROWS_A) ? aw[row] : tw[row - NROWS_A];
    ((float4*)g_buf0)[row * 64 + c4] = ((const float4*)emb)[word * 64 + c4];
}

// ---------------------------------------------------------------------------
// Weight prep: w[(tap*256+d)*512 + n] -> wt[bn][tap*256+d], hi/lo bf16 split.
// bn interleaves GLU partners: bn = 2*(n&255) + (n>>8)  (a at even, g at odd)
// ---------------------------------------------------------------------------
__global__ void wprep_kernel(const float* __restrict__ exp_w, const float* __restrict__ ref_w) {
    int layer = blockIdx.z;
    const float* w = (layer < 7) ? exp_w + (size_t)layer * KTOT * TWOD
                                 : ref_w + (size_t)(layer - 7) * KTOT * TWOD;
    __shared__ float tile[32][33];
    int kk0 = blockIdx.x * 32, n0 = blockIdx.y * 32;
    int tx = threadIdx.x, ty = threadIdx.y;
    #pragma unroll
    for (int j = 0; j < 4; ++j)
        tile[ty + j * 8][tx] = w[(size_t)(kk0 + ty + j * 8) * TWOD + n0 + tx];
    __syncthreads();
    #pragma unroll
    for (int j = 0; j < 4; ++j) {
        int n = n0 + ty + j * 8, kk = kk0 + tx;
        float v = tile[tx][ty + j * 8];
        __nv_bfloat16 h = __float2bfloat16(v);
        __nv_bfloat16 l = __float2bfloat16(v - __bfloat162float(h));
        int bn = 2 * (n & 255) + (n >> 8);
        size_t o = (size_t)layer * TWOD * KTOT + (size_t)bn * KTOT + kk;
        g_wt_hi[o] = h; g_wt_lo[o] = l;
    }
}

// ---------------------------------------------------------------------------
// Activation split (only needed once, on the embedding output)
// ---------------------------------------------------------------------------
__global__ void xprep_kernel(const float* __restrict__ x) {
    int gi = blockIdx.x * blockDim.x + threadIdx.x;       // 16B group index
    const float4* s = (const float4*)x + (size_t)gi * 2;
    float4 v0 = s[0], v1 = s[1];
    float f[8] = {v0.x, v0.y, v0.z, v0.w, v1.x, v1.y, v1.z, v1.w};
    uint32_t hp[4], lp[4];
    #pragma unroll
    for (int j = 0; j < 4; ++j) {
        __nv_bfloat162 h2 = __floats2bfloat162_rn(f[2*j], f[2*j+1]);
        float r0 = f[2*j]   - __low2float(h2);
        float r1 = f[2*j+1] - __high2float(h2);
        __nv_bfloat162 l2 = __floats2bfloat162_rn(r0, r1);
        hp[j] = *reinterpret_cast<uint32_t*>(&h2);
        lp[j] = *reinterpret_cast<uint32_t*>(&l2);
    }
    ((uint4*)g_xh0)[gi] = make_uint4(hp[0], hp[1], hp[2], hp[3]);
    ((uint4*)g_xl0)[gi] = make_uint4(lp[0], lp[1], lp[2], lp[3]);
}

// ---------------------------------------------------------------------------
// bf16 mma.sync conv+GLU res-block, ldmatrix fragment loads, 2 CTAs/SM.
// Block tile M=128 x N=128 (64 GLU pairs interleaved a,g) x K=768 (chunks of 32).
// Epilogue writes fp32 out AND the bf16 hi/lo split into the *other* buffer pair
// (ping-pong -> no cross-block race with this layer's reads).
// ---------------------------------------------------------------------------
__global__ __launch_bounds__(256, 2) void conv_mma_kernel(
    const __nv_bfloat16* __restrict__ xh, const __nv_bfloat16* __restrict__ xl,
    const float* __restrict__ xin, float* __restrict__ xout,
    __nv_bfloat16* __restrict__ xho, __nv_bfloat16* __restrict__ xlo,
    const __nv_bfloat16* __restrict__ wh, const __nv_bfloat16* __restrict__ wl,
    const float* __restrict__ bias, int dil)
{
    extern __shared__ char dsm[];
    const uint32_t smb = smem_u32(dsm);
    const int tid = threadIdx.x;
    const int lane = tid & 31, wid = tid >> 5;
    const int wm = wid & 1, wn = wid >> 1;       // 2 x 4 warp grid
    const int cg = blockIdx.y;                   // 64 GLU pairs per group

    const int t = blockIdx.x;
    int base, l0, L;
    if (t < 128) { int s = t >> 3;         l0 = (t & 7) << 7;         base = s * AA;           L = AA; }
    else         { int s = (t - 128) >> 2; l0 = ((t - 128) & 3) << 7; base = NROWS_A + s * TT; L = TT; }

    const int lr  = tid >> 2;       // 0..63 loader row
    const int seg = tid & 3;        // 16B segment

    float d[4][4][4];
    #pragma unroll
    for (int i = 0; i < 4; ++i)
        #pragma unroll
        for (int j = 0; j < 4; ++j)
            #pragma unroll
            for (int u = 0; u < 4; ++u) d[i][j][u] = 0.f;

    // ldmatrix lane addressing
    const int quad  = lane >> 3;
    const int arow  = (lane & 7) + ((quad & 1) << 3);
    const int acb   = (quad >> 1) << 4;
    const int brow  = (lane & 7) + ((lane >> 4) << 3);
    const int bcb   = ((lane >> 3) & 1) << 4;

    // ---- chunk loader ----
    auto load_chunk = [&](int ci, int stage) {
        const int tap = ci >> 3;
        const int dc  = (ci & 7) * 32;
        const int off = (tap - 1) * dil;
        const uint32_t st = smb + stage * STAGE_BYTES;
        const int kk = tap * 256 + dc;
        #pragma unroll
        for (int i = 0; i < 2; ++i) {
            int r = lr + i * 64;
            int ll = l0 + r + off;
            uint32_t sz = (ll >= 0 && ll < L) ? 16u : 0u;
            int grow = base + (sz ? ll : 0);
            const char* sa_h = (const char*)(xh + (size_t)grow * DD + dc) + seg * 16;
            const char* sa_l = (const char*)(xl + (size_t)grow * DD + dc) + seg * 16;
            uint32_t da = st + A_HI + r * 80 + seg * 16;
            cpa16(da, sa_h, sz);
            cpa16(da + (A_LO - A_HI), sa_l, sz);
            const char* sb_h = (const char*)(wh + (size_t)(cg * 128 + r) * KTOT + kk) + seg * 16;
            const char* sb_l = (const char*)(wl + (size_t)(cg * 128 + r) * KTOT + kk) + seg * 16;
            uint32_t db = st + B_HI + r * 80 + seg * 16;
            cpa16(db, sb_h, 16u);
            cpa16(db + (B_LO - B_HI), sb_l, 16u);
        }
    };

    load_chunk(0, 0);
    CP_COMMIT();

    for (int ci = 0; ci < 24; ++ci) {
        if (ci < 23) { load_chunk(ci + 1, (ci + 1) & 1); CP_COMMIT(); CP_WAIT1(); }
        else         { CP_WAIT0(); }
        __syncthreads();

        const uint32_t st = smb + (ci & 1) * STAGE_BYTES;
        #pragma unroll
        for (int ks = 0; ks < 2; ++ks) {
            const uint32_t kso = ks * 32;
            #pragma unroll
            for (int ntp = 0; ntp < 2; ++ntp) {
                uint32_t pb = st + (wn * 32 + ntp * 16 + brow) * 80 + kso + bcb;
                uint32_t bh[4], bl[4];
                LDMX4(bh, pb + B_HI);
                LDMX4(bl, pb + B_LO);
                #pragma unroll
                for (int mt = 0; mt < 4; ++mt) {
                    uint32_t pa = st + (wm * 64 + mt * 16 + arow) * 80 + kso + acb;
                    uint32_t ahi[4], alo[4];
                    LDMX4(ahi, pa + A_HI);
                    LDMX4(alo, pa + A_LO);
                    #pragma unroll
                    for (int h = 0; h < 2; ++h) {
                        const int nt = ntp * 2 + h;
                        MMA_BF16(d[mt][nt], ahi, bh[2*h], bh[2*h+1]);
                        MMA_BF16(d[mt][nt], alo, bh[2*h], bh[2*h+1]);
                        MMA_BF16(d[mt][nt], ahi, bl[2*h], bl[2*h+1]);
                    }
                }
            }
        }
        __syncthreads();
    }

    // ---- epilogue: GLU + residual + bf16 hi/lo split for next layer ----
    #pragma unroll
    for (int nt = 0; nt < 4; ++nt) {
        const int p  = cg * 64 + wn * 16 + nt * 4 + (lane & 3);
        const float ba = bias[p], bg = bias[DD + p];
        #pragma unroll
        for (int mt = 0; mt < 4; ++mt) {
            const int r0 = base + l0 + wm * 64 + mt * 16 + (lane >> 2);
            #pragma unroll
            for (int hh = 0; hh < 2; ++hh) {
                const size_t idx = (size_t)(r0 + hh * 8) * DD + p;
                float a = d[mt][nt][2*hh]     + ba;
                float g = d[mt][nt][2*hh + 1] + bg;
                float o = xin[idx] + a * (1.f / (1.f + expf(-g)));
                xout[idx] = o;
                __nv_bfloat16 h = __float2bfloat16(o);
                xho[idx] = h;
                xlo[idx] = __float2bfloat16(o - __bfloat162float(h));
            }
        }
    }
}

// ---------------------------------------------------------------------------
// Per-row squared norm
// ---------------------------------------------------------------------------
__global__ void sqnorm_kernel(const float* __restrict__ x) {
    int row = blockIdx.x;
    int lane = threadIdx.x;
    const float4* r4 = (const float4*)(x + (size_t)row * DD);
    float s = 0.f;
    #pragma unroll
    for (int i = 0; i < 2; ++i) {
        float4 v = r4[lane + i * 32];
        s += v.x*v.x + v.y*v.y + v.z*v.z + v.w*v.w;
    }
    #pragma unroll
    for (int o = 16; o; o >>= 1) s += __shfl_xor_sync(0xffffffffu, s, o);
    if (lane == 0) g_sq[row] = s;
}

// ---------------------------------------------------------------------------
// Fused dist -> S -> rowmax
// ---------------------------------------------------------------------------
__global__ __launch_bounds__(256) void dist_rowmax_kernel(
    const float* __restrict__ x, const float* __restrict__ am, const float* __restrict__ tm)
{
    const int b = blockIdx.y;
    const int a0 = blockIdx.x << 6;
    const int tid = threadIdx.x, tx = tid & 15, ty = tid >> 4;

    __shared__ float arts[64][33];
    __shared__ float tps[64][33];
    __shared__ float a2s[64], ams[64], t2s[64], tms[64];
    __shared__ float red[64][17];

    const int abase = b * AA + a0;
    const int tbase = NROWS_A + b * TT;

    if (tid < 64) {
        a2s[tid] = g_sq[abase + tid];
        ams[tid] = am[b * AA + a0 + tid];
    }
    float lm[4] = {0.f, 0.f, 0.f, 0.f};

    for (int t0 = 0; t0 < TT; t0 += 64) {
        if (tid < 64) {
            t2s[tid] = g_sq[tbase + t0 + tid];
            tms[tid] = tm[b * TT + t0 + tid];
        }
        float acc[4][4] = {};
        for (int dc = 0; dc < DD; dc += 32) {
            #pragma unroll
            for (int s = 0; s < 8; ++s) {
                int e = tid + s * 256;
                int l = e >> 5, c = e & 31;
                arts[l][c] = x[(size_t)(abase + l) * DD + dc + c];
                tps[l][c]  = x[(size_t)(tbase + t0 + l) * DD + dc + c];
            }
            __syncthreads();
            #pragma unroll
            for (int dd = 0; dd < 32; ++dd) {
                float ar[4], tr[4];
                #pragma unroll
                for (int i = 0; i < 4; ++i) ar[i] = arts[ty * 4 + i][dd];
                #pragma unroll
                for (int j = 0; j < 4; ++j) tr[j] = tps[tx * 4 + j][dd];
                #pragma unroll
                for (int i = 0; i < 4; ++i)
                    #pragma unroll
                    for (int j = 0; j < 4; ++j)
                        acc[i][j] = fmaf(ar[i], tr[j], acc[i][j]);
            }
            __syncthreads();
        }
        #pragma unroll
        for (int i = 0; i < 4; ++i) {
            int r = ty * 4 + i;
            #pragma unroll
            for (int j = 0; j < 4; ++j) {
                int tj = tx * 4 + j;
                float dist = a2s[r] + t2s[tj] - 2.f * acc[i][j];
                dist = fmaxf(dist, 0.f);
                float S = expf(-dist) * ams[r] * tms[tj];
                lm[i] = fmaxf(lm[i], S);
            }
        }
        __syncthreads();
    }

    #pragma unroll
    for (int i = 0; i < 4; ++i) red[ty * 4 + i][tx] = lm[i];
    __syncthreads();
    if (tid < 64) {
        float m = red[tid][0];
        #pragma unroll
        for (int xx = 1; xx < 16; ++xx) m = fmaxf(m, red[tid][xx]);
        g_rowmax[b * AA + a0 + tid] = m;
    }
}

// ---------------------------------------------------------------------------
// Top-10 + tiny MLP
// ---------------------------------------------------------------------------
__global__ __launch_bounds__(256) void topk_ff_kernel(
    const float* __restrict__ f1w, const float* __restrict__ f1b,
    const float* __restrict__ f2w, const float* __restrict__ f2b,
    float* __restrict__ out)
{
    const int b = blockIdx.x;
    const int tid = threadIdx.x;
    __shared__ float vals[AA];
    __shared__ float sv[256];
    __shared__ int   si[256];
    __shared__ float top[10];

    #pragma unroll
    for (int s = 0; s < 4; ++s) vals[tid + s * 256] = g_rowmax[b * AA + tid + s * 256];
    __syncthreads();

    for (int it = 0; it < 10; ++it) {
        float v = -1.f; int idx = 1 << 20;
        #pragma unroll
        for (int s = 0; s < 4; ++s) {
            int i = s * 256 + tid;
            float xv = vals[i];
            if (xv > v || (xv == v && i < idx)) { v = xv; idx = i; }
        }
        sv[tid] = v; si[tid] = idx;
        __syncthreads();
        for (int o = 128; o; o >>= 1) {
            if (tid < o) {
                if (sv[tid+o] > sv[tid] || (sv[tid+o] == sv[tid] && si[tid+o] < si[tid])) {
                    sv[tid] = sv[tid+o]; si[tid] = si[tid+o];
                }
            }
            __syncthreads();
        }
        if (tid == 0) { top[it] = sv[0]; vals[si[0]] = -1.f; }
        __syncthreads();
    }

    if (tid == 0) {
        float o = f2b[0];
        #pragma unroll
        for (int j = 0; j < 10; ++j) {
            float h = f1b[j];
            #pragma unroll
            for (int i = 0; i < 10; ++i) h += top[i] * f1w[i * 10 + j];
            h = fmaxf(h, 0.f);
            o += h * f2w[j];
        }
        out[b] = o;
    }
}

// ---------------------------------------------------------------------------
// Launch
// ---------------------------------------------------------------------------
extern "C" void kernel_launch(void* const* d_in, const int* in_sizes, int n_in,
                              void* d_out, int out_size) {
    const int*   aw    = (const int*)d_in[0];
    const int*   tw    = (const int*)d_in[2];
    const float* am    = (const float*)d_in[4];
    const float* tm    = (const float*)d_in[5];
    const float* emb   = (const float*)d_in[6];
    const float* exp_w = (const float*)d_in[7];
    const float* exp_b = (const float*)d_in[8];
    const float* ref_w = (const float*)d_in[9];
    const float* ref_b = (const float*)d_in[10];
    const float* f1w   = (const float*)d_in[11];
    const float* f1b   = (const float*)d_in[12];
    const float* f2w   = (const float*)d_in[13];
    const float* f2b   = (const float*)d_in[14];
    float* out = (float*)d_out;

    float *b0 = nullptr, *b1 = nullptr;
    __nv_bfloat16 *xh0 = nullptr, *xl0 = nullptr, *xh1 = nullptr, *xl1 = nullptr;
    __nv_bfloat16 *wh = nullptr, *wl = nullptr;
    cudaGetSymbolAddress((void**)&b0, g_buf0);
    cudaGetSymbolAddress((void**)&b1, g_buf1);
    cudaGetSymbolAddress((void**)&xh0, g_xh0);
    cudaGetSymbolAddress((void**)&xl0, g_xl0);
    cudaGetSymbolAddress((void**)&xh1, g_xh1);
    cudaGetSymbolAddress((void**)&xl1, g_xl1);
    cudaGetSymbolAddress((void**)&wh, g_wt_hi);
    cudaGetSymbolAddress((void**)&wl, g_wt_lo);

    cudaFuncSetAttribute(conv_mma_kernel, cudaFuncAttributeMaxDynamicSharedMemorySize, CONV_SMEM);

    embed_kernel<<<(NROWS * 64) / 256, 256>>>(aw, tw, emb);
    wprep_kernel<<<dim3(KTOT / 32, TWOD / 32, NLAYER), dim3(32, 8)>>>(exp_w, ref_w);
    xprep_kernel<<<(NROWS * DD / 8) / 256, 256>>>(b0);

    const int dils[10] = {1, 2, 4, 8, 16, 32, 32, 1, 1, 1};
    float* src = b0;
    float* dst = b1;
    __nv_bfloat16 *hs = xh0, *ls = xl0, *hd = xh1, *ld = xl1;
    for (int i = 0; i < 10; ++i) {
        const float* bs = (i < 7) ? exp_b + i * TWOD : ref_b + (i - 7) * TWOD;
        conv_mma_kernel<<<dim3(192, 4), 256, CONV_SMEM>>>(
            hs, ls, src, dst, hd, ld,
            wh + (size_t)i * TWOD * KTOT, wl + (size_t)i * TWOD * KTOT, bs, dils[i]);
        float* tf = src; src = dst; dst = tf;
        __nv_bfloat16* th = hs; hs = hd; hd = th;
        __nv_bfloat16* tl = ls; ls = ld; ld = tl;
    }
    // 10 swaps (even) -> final encodings in b0 == src
    sqnorm_kernel<<<NROWS, 32>>>(src);
    dist_rowmax_kernel<<<dim3(16, 16), 256>>>(src, am, tm);
    topk_ff_kernel<<<16, 256>>>(f1w, f1b, f2w, f2b, out);
}

// round 11
// speedup vs baseline: 2.4220x; 1.0227x over previous
#include <cuda_runtime.h>
#include <cuda_bf16.h>
#include <math.h>
#include <stdint.h>

#define BB 16
#define AA 1024
#define TT 512
#define DD 256
#define TWOD 512
#define KTOT 768                     /* 3 taps * 256 channels */
#define NROWS_A (BB*AA)              /* 16384 */
#define NROWS_T (BB*TT)              /* 8192  */
#define NROWS   (NROWS_A+NROWS_T)    /* 24576 */
#define NLAYER 10

// ---------------- static device scratch (no runtime allocation) ----------------
__device__ float g_buf0[(size_t)NROWS * DD];
__device__ float g_buf1[(size_t)NROWS * DD];
__device__ __nv_bfloat16 g_xh0[(size_t)NROWS * DD];
__device__ __nv_bfloat16 g_xl0[(size_t)NROWS * DD];
__device__ __nv_bfloat16 g_xh1[(size_t)NROWS * DD];
__device__ __nv_bfloat16 g_xl1[(size_t)NROWS * DD];
__device__ __nv_bfloat16 g_wt_hi[(size_t)NLAYER * TWOD * KTOT];
__device__ __nv_bfloat16 g_wt_lo[(size_t)NLAYER * TWOD * KTOT];
__device__ float g_sq[NROWS];
__device__ float g_rowmax[NROWS_A];

// ---------------- helpers ----------------
__device__ __forceinline__ uint32_t smem_u32(const void* p) {
    uint32_t a;
    asm("{ .reg .u64 t; cvta.to.shared.u64 t, %1; cvt.u32.u64 %0, t; }" : "=r"(a) : "l"(p));
    return a;
}
__device__ __forceinline__ void cpa16(uint32_t dst, const void* src, uint32_t sz) {
    asm volatile("cp.async.ca.shared.global [%0], [%1], 16, %2;"
                 :: "r"(dst), "l"(src), "r"(sz) : "memory");
}
#define CP_COMMIT() asm volatile("cp.async.commit_group;" ::: "memory")
#define CP_WAIT0()  asm volatile("cp.async.wait_group 0;" ::: "memory")

#define MMA_BF16(dd, a, b0, b1)                                              \
    asm volatile("mma.sync.aligned.m16n8k16.row.col.f32.bf16.bf16.f32 "      \
        "{%0,%1,%2,%3}, {%4,%5,%6,%7}, {%8,%9}, {%0,%1,%2,%3};"              \
        : "+f"((dd)[0]), "+f"((dd)[1]), "+f"((dd)[2]), "+f"((dd)[3])         \
        : "r"((a)[0]), "r"((a)[1]), "r"((a)[2]), "r"((a)[3]), "r"(b0), "r"(b1))

#define LDMX4(r, a)                                                          \
    asm volatile("ldmatrix.sync.aligned.m8n8.x4.shared.b16 {%0,%1,%2,%3}, [%4];" \
        : "=r"((r)[0]), "=r"((r)[1]), "=r"((r)[2]), "=r"((r)[3]) : "r"(a))

// smem stage layout (bytes), padded row stride 80B (=40 bf16) -> conflict-free
#define A_HI 0
#define A_LO 10240
#define B_HI 20480
#define B_LO 30720
#define STAGE_BYTES 40960
#define CONV_SMEM (2 * STAGE_BYTES)

// ---------------------------------------------------------------------------
// Embedding gather
// ---------------------------------------------------------------------------
__global__ void embed_kernel(const int* __restrict__ aw, const int* __restrict__ tw,
                             const float* __restrict__ emb) {
    int gi  = blockIdx.x * blockDim.x + threadIdx.x;
    int row = gi >> 6;
    int c4  = gi & 63;
    int word = (row < NROWS_A) ? aw[row] : tw[row - NROWS_A];
    ((float4*)g_buf0)[row * 64 + c4] = ((const float4*)emb)[word * 64 + c4];
}

// ---------------------------------------------------------------------------
// Weight prep: w[(tap*256+d)*512 + n] -> wt[bn][tap*256+d], hi/lo bf16 split.
// bn interleaves GLU partners: bn = 2*(n&255) + (n>>8)  (a at even, g at odd)
// ---------------------------------------------------------------------------
__global__ void wprep_kernel(const float* __restrict__ exp_w, const float* __restrict__ ref_w) {
    int layer = blockIdx.z;
    const float* w = (layer < 7) ? exp_w + (size_t)layer * KTOT * TWOD
                                 : ref_w + (size_t)(layer - 7) * KTOT * TWOD;
    __shared__ float tile[32][33];
    int kk0 = blockIdx.x * 32, n0 = blockIdx.y * 32;
    int tx = threadIdx.x, ty = threadIdx.y;
    #pragma unroll
    for (int j = 0; j < 4; ++j)
        tile[ty + j * 8][tx] = w[(size_t)(kk0 + ty + j * 8) * TWOD + n0 + tx];
    __syncthreads();
    #pragma unroll
    for (int j = 0; j < 4; ++j) {
        int n = n0 + ty + j * 8, kk = kk0 + tx;
        float v = tile[tx][ty + j * 8];
        __nv_bfloat16 h = __float2bfloat16(v);
        __nv_bfloat16 l = __float2bfloat16(v - __bfloat162float(h));
        int bn = 2 * (n & 255) + (n >> 8);
        size_t o = (size_t)layer * TWOD * KTOT + (size_t)bn * KTOT + kk;
        g_wt_hi[o] = h; g_wt_lo[o] = l;
    }
}

// ---------------------------------------------------------------------------
// Activation split (only needed once, on the embedding output)
// ---------------------------------------------------------------------------
__global__ void xprep_kernel(const float* __restrict__ x) {
    int gi = blockIdx.x * blockDim.x + threadIdx.x;       // 16B group index
    const float4* s = (const float4*)x + (size_t)gi * 2;
    float4 v0 = s[0], v1 = s[1];
    float f[8] = {v0.x, v0.y, v0.z, v0.w, v1.x, v1.y, v1.z, v1.w};
    uint32_t hp[4], lp[4];
    #pragma unroll
    for (int j = 0; j < 4; ++j) {
        __nv_bfloat162 h2 = __floats2bfloat162_rn(f[2*j], f[2*j+1]);
        float r0 = f[2*j]   - __low2float(h2);
        float r1 = f[2*j+1] - __high2float(h2);
        __nv_bfloat162 l2 = __floats2bfloat162_rn(r0, r1);
        hp[j] = *reinterpret_cast<uint32_t*>(&h2);
        lp[j] = *reinterpret_cast<uint32_t*>(&l2);
    }
    ((uint4*)g_xh0)[gi] = make_uint4(hp[0], hp[1], hp[2], hp[3]);
    ((uint4*)g_xl0)[gi] = make_uint4(lp[0], lp[1], lp[2], lp[3]);
}

// ---------------------------------------------------------------------------
// bf16 mma.sync conv+GLU res-block.
// Block tile M=128 x N=128 (64 GLU pairs interleaved a,g) x K=768 (chunks of 32).
// Warp grid 4(M) x 2(N), warp tile 32x64: A fragments held across N loop
// (24 ldmatrix/warp/chunk instead of 40). ONE barrier per chunk; loads for
// chunk ci+1 issued right after the barrier, overlapping compute of ci.
// ---------------------------------------------------------------------------
__global__ __launch_bounds__(256, 2) void conv_mma_kernel(
    const __nv_bfloat16* __restrict__ xh, const __nv_bfloat16* __restrict__ xl,
    const float* __restrict__ xin, float* __restrict__ xout,
    __nv_bfloat16* __restrict__ xho, __nv_bfloat16* __restrict__ xlo,
    const __nv_bfloat16* __restrict__ wh, const __nv_bfloat16* __restrict__ wl,
    const float* __restrict__ bias, int dil)
{
    extern __shared__ char dsm[];
    const uint32_t smb = smem_u32(dsm);
    const int tid = threadIdx.x;
    const int lane = tid & 31, wid = tid >> 5;
    const int wm = wid & 3, wn = wid >> 2;       // 4 x 2 warp grid
    const int cg = blockIdx.y;                   // 64 GLU pairs per group

    const int t = blockIdx.x;
    int base, l0, L;
    if (t < 128) { int s = t >> 3;         l0 = (t & 7) << 7;         base = s * AA;           L = AA; }
    else         { int s = (t - 128) >> 2; l0 = ((t - 128) & 3) << 7; base = NROWS_A + s * TT; L = TT; }

    const int lr  = tid >> 2;       // 0..63 loader row
    const int seg = tid & 3;        // 16B segment

    float d[2][8][4];
    #pragma unroll
    for (int i = 0; i < 2; ++i)
        #pragma unroll
        for (int j = 0; j < 8; ++j)
            #pragma unroll
            for (int u = 0; u < 4; ++u) d[i][j][u] = 0.f;

    // ldmatrix lane addressing
    const int quad  = lane >> 3;
    const int arow  = (lane & 7) + ((quad & 1) << 3);
    const int acb   = (quad >> 1) << 4;
    const int brow  = (lane & 7) + ((lane >> 4) << 3);
    const int bcb   = ((lane >> 3) & 1) << 4;

    // ---- chunk loader ----
    auto load_chunk = [&](int ci, int stage) {
        const int tap = ci >> 3;
        const int dc  = (ci & 7) * 32;
        const int off = (tap - 1) * dil;
        const uint32_t st = smb + stage * STAGE_BYTES;
        const int kk = tap * 256 + dc;
        #pragma unroll
        for (int i = 0; i < 2; ++i) {
            int r = lr + i * 64;
            int ll = l0 + r + off;
            uint32_t sz = (ll >= 0 && ll < L) ? 16u : 0u;
            int grow = base + (sz ? ll : 0);
            const char* sa_h = (const char*)(xh + (size_t)grow * DD + dc) + seg * 16;
            const char* sa_l = (const char*)(xl + (size_t)grow * DD + dc) + seg * 16;
            uint32_t da = st + A_HI + r * 80 + seg * 16;
            cpa16(da, sa_h, sz);
            cpa16(da + (A_LO - A_HI), sa_l, sz);
            const char* sb_h = (const char*)(wh + (size_t)(cg * 128 + r) * KTOT + kk) + seg * 16;
            const char* sb_l = (const char*)(wl + (size_t)(cg * 128 + r) * KTOT + kk) + seg * 16;
            uint32_t db = st + B_HI + r * 80 + seg * 16;
            cpa16(db, sb_h, 16u);
            cpa16(db + (B_LO - B_HI), sb_l, 16u);
        }
    };

    load_chunk(0, 0);
    CP_COMMIT();

    for (int ci = 0; ci < 24; ++ci) {
        CP_WAIT0();          // chunk ci's loads (committed last iteration) done
        __syncthreads();     // publish them; also: all warps done computing ci-1
        if (ci < 23) { load_chunk(ci + 1, (ci + 1) & 1); CP_COMMIT(); }

        const uint32_t st = smb + (ci & 1) * STAGE_BYTES;
        #pragma unroll
        for (int ks = 0; ks < 2; ++ks) {
            const uint32_t kso = ks * 32;
            uint32_t ahi[2][4], alo[2][4];
            #pragma unroll
            for (int mt = 0; mt < 2; ++mt) {
                uint32_t pa = st + (wm * 32 + mt * 16 + arow) * 80 + kso + acb;
                LDMX4(ahi[mt], pa + A_HI);
                LDMX4(alo[mt], pa + A_LO);
            }
            #pragma unroll
            for (int ntp = 0; ntp < 4; ++ntp) {
                uint32_t pb = st + (wn * 64 + ntp * 16 + brow) * 80 + kso + bcb;
                uint32_t bh[4], bl[4];
                LDMX4(bh, pb + B_HI);
                LDMX4(bl, pb + B_LO);
                #pragma unroll
                for (int mt = 0; mt < 2; ++mt)
                    #pragma unroll
                    for (int h = 0; h < 2; ++h) {
                        const int nt = ntp * 2 + h;
                        MMA_BF16(d[mt][nt], ahi[mt], bh[2*h], bh[2*h+1]);
                        MMA_BF16(d[mt][nt], alo[mt], bh[2*h], bh[2*h+1]);
                        MMA_BF16(d[mt][nt], ahi[mt], bl[2*h], bl[2*h+1]);
                    }
            }
        }
    }

    // ---- epilogue: GLU + residual + bf16 hi/lo split for next layer ----
    #pragma unroll
    for (int nt = 0; nt < 8; ++nt) {
        const int p  = cg * 64 + wn * 32 + nt * 4 + (lane & 3);
        const float ba = bias[p], bg = bias[DD + p];
        #pragma unroll
        for (int mt = 0; mt < 2; ++mt) {
            const int r0 = base + l0 + wm * 32 + mt * 16 + (lane >> 2);
            #pragma unroll
            for (int hh = 0; hh < 2; ++hh) {
                const size_t idx = (size_t)(r0 + hh * 8) * DD + p;
                float a = d[mt][nt][2*hh]     + ba;
                float g = d[mt][nt][2*hh + 1] + bg;
                float o = xin[idx] + a * (1.f / (1.f + expf(-g)));
                xout[idx] = o;
                __nv_bfloat16 h = __float2bfloat16(o);
                xho[idx] = h;
                xlo[idx] = __float2bfloat16(o - __bfloat162float(h));
            }
        }
    }
}

// ---------------------------------------------------------------------------
// Per-row squared norm
// ---------------------------------------------------------------------------
__global__ void sqnorm_kernel(const float* __restrict__ x) {
    int row = blockIdx.x;
    int lane = threadIdx.x;
    const float4* r4 = (const float4*)(x + (size_t)row * DD);
    float s = 0.f;
    #pragma unroll
    for (int i = 0; i < 2; ++i) {
        float4 v = r4[lane + i * 32];
        s += v.x*v.x + v.y*v.y + v.z*v.z + v.w*v.w;
    }
    #pragma unroll
    for (int o = 16; o; o >>= 1) s += __shfl_xor_sync(0xffffffffu, s, o);
    if (lane == 0) g_sq[row] = s;
}

// ---------------------------------------------------------------------------
// Fused dist -> S -> rowmax
// ---------------------------------------------------------------------------
__global__ __launch_bounds__(256) void dist_rowmax_kernel(
    const float* __restrict__ x, const float* __restrict__ am, const float* __restrict__ tm)
{
    const int b = blockIdx.y;
    const int a0 = blockIdx.x << 6;
    const int tid = threadIdx.x, tx = tid & 15, ty = tid >> 4;

    __shared__ float arts[64][33];
    __shared__ float tps[64][33];
    __shared__ float a2s[64], ams[64], t2s[64], tms[64];
    __shared__ float red[64][17];

    const int abase = b * AA + a0;
    const int tbase = NROWS_A + b * TT;

    if (tid < 64) {
        a2s[tid] = g_sq[abase + tid];
        ams[tid] = am[b * AA + a0 + tid];
    }
    float lm[4] = {0.f, 0.f, 0.f, 0.f};

    for (int t0 = 0; t0 < TT; t0 += 64) {
        if (tid < 64) {
            t2s[tid] = g_sq[tbase + t0 + tid];
            tms[tid] = tm[b * TT + t0 + tid];
        }
        float acc[4][4] = {};
        for (int dc = 0; dc < DD; dc += 32) {
            #pragma unroll
            for (int s = 0; s < 8; ++s) {
                int e = tid + s * 256;
                int l = e >> 5, c = e & 31;
                arts[l][c] = x[(size_t)(abase + l) * DD + dc + c];
                tps[l][c]  = x[(size_t)(tbase + t0 + l) * DD + dc + c];
            }
            __syncthreads();
            #pragma unroll
            for (int dd = 0; dd < 32; ++dd) {
                float ar[4], tr[4];
                #pragma unroll
                for (int i = 0; i < 4; ++i) ar[i] = arts[ty * 4 + i][dd];
                #pragma unroll
                for (int j = 0; j < 4; ++j) tr[j] = tps[tx * 4 + j][dd];
                #pragma unroll
                for (int i = 0; i < 4; ++i)
                    #pragma unroll
                    for (int j = 0; j < 4; ++j)
                        acc[i][j] = fmaf(ar[i], tr[j], acc[i][j]);
            }
            __syncthreads();
        }
        #pragma unroll
        for (int i = 0; i < 4; ++i) {
            int r = ty * 4 + i;
            #pragma unroll
            for (int j = 0; j < 4; ++j) {
                int tj = tx * 4 + j;
                float dist = a2s[r] + t2s[tj] - 2.f * acc[i][j];
                dist = fmaxf(dist, 0.f);
                float S = expf(-dist) * ams[r] * tms[tj];
                lm[i] = fmaxf(lm[i], S);
            }
        }
        __syncthreads();
    }

    #pragma unroll
    for (int i = 0; i < 4; ++i) red[ty * 4 + i][tx] = lm[i];
    __syncthreads();
    if (tid < 64) {
        float m = red[tid][0];
        #pragma unroll
        for (int xx = 1; xx < 16; ++xx) m = fmaxf(m, red[tid][xx]);
        g_rowmax[b * AA + a0 + tid] = m;
    }
}

// ---------------------------------------------------------------------------
// Top-10 + tiny MLP
// ---------------------------------------------------------------------------
__global__ __launch_bounds__(256) void topk_ff_kernel(
    const float* __restrict__ f1w, const float* __restrict__ f1b,
    const float* __restrict__ f2w, const float* __restrict__ f2b,
    float* __restrict__ out)
{
    const int b = blockIdx.x;
    const int tid = threadIdx.x;
    __shared__ float vals[AA];
    __shared__ float sv[256];
    __shared__ int   si[256];
    __shared__ float top[10];

    #pragma unroll
    for (int s = 0; s < 4; ++s) vals[tid + s * 256] = g_rowmax[b * AA + tid + s * 256];
    __syncthreads();

    for (int it = 0; it < 10; ++it) {
        float v = -1.f; int idx = 1 << 20;
        #pragma unroll
        for (int s = 0; s < 4; ++s) {
            int i = s * 256 + tid;
            float xv = vals[i];
            if (xv > v || (xv == v && i < idx)) { v = xv; idx = i; }
        }
        sv[tid] = v; si[tid] = idx;
        __syncthreads();
        for (int o = 128; o; o >>= 1) {
            if (tid < o) {
                if (sv[tid+o] > sv[tid] || (sv[tid+o] == sv[tid] && si[tid+o] < si[tid])) {
                    sv[tid] = sv[tid+o]; si[tid] = si[tid+o];
                }
            }
            __syncthreads();
        }
        if (tid == 0) { top[it] = sv[0]; vals[si[0]] = -1.f; }
        __syncthreads();
    }

    if (tid == 0) {
        float o = f2b[0];
        #pragma unroll
        for (int j = 0; j < 10; ++j) {
            float h = f1b[j];
            #pragma unroll
            for (int i = 0; i < 10; ++i) h += top[i] * f1w[i * 10 + j];
            h = fmaxf(h, 0.f);
            o += h * f2w[j];
        }
        out[b] = o;
    }
}

// ---------------------------------------------------------------------------
// Launch
// ---------------------------------------------------------------------------
extern "C" void kernel_launch(void* const* d_in, const int* in_sizes, int n_in,
                              void* d_out, int out_size) {
    const int*   aw    = (const int*)d_in[0];
    const int*   tw    = (const int*)d_in[2];
    const float* am    = (const float*)d_in[4];
    const float* tm    = (const float*)d_in[5];
    const float* emb   = (const float*)d_in[6];
    const float* exp_w = (const float*)d_in[7];
    const float* exp_b = (const float*)d_in[8];
    const float* ref_w = (const float*)d_in[9];
    const float* ref_b = (const float*)d_in[10];
    const float* f1w   = (const float*)d_in[11];
    const float* f1b   = (const float*)d_in[12];
    const float* f2w   = (const float*)d_in[13];
    const float* f2b   = (const float*)d_in[14];
    float* out = (float*)d_out;

    float *b0 = nullptr, *b1 = nullptr;
    __nv_bfloat16 *xh0 = nullptr, *xl0 = nullptr, *xh1 = nullptr, *xl1 = nullptr;
    __nv_bfloat16 *wh = nullptr, *wl = nullptr;
    cudaGetSymbolAddress((void**)&b0, g_buf0);
    cudaGetSymbolAddress((void**)&b1, g_buf1);
    cudaGetSymbolAddress((void**)&xh0, g_xh0);
    cudaGetSymbolAddress((void**)&xl0, g_xl0);
    cudaGetSymbolAddress((void**)&xh1, g_xh1);
    cudaGetSymbolAddress((void**)&xl1, g_xl1);
    cudaGetSymbolAddress((void**)&wh, g_wt_hi);
    cudaGetSymbolAddress((void**)&wl, g_wt_lo);

    cudaFuncSetAttribute(conv_mma_kernel, cudaFuncAttributeMaxDynamicSharedMemorySize, CONV_SMEM);

    embed_kernel<<<(NROWS * 64) / 256, 256>>>(aw, tw, emb);
    wprep_kernel<<<dim3(KTOT / 32, TWOD / 32, NLAYER), dim3(32, 8)>>>(exp_w, ref_w);
    xprep_kernel<<<(NROWS * DD / 8) / 256, 256>>>(b0);

    const int dils[10] = {1, 2, 4, 8, 16, 32, 32, 1, 1, 1};
    float* src = b0;
    float* dst = b1;
    __nv_bfloat16 *hs = xh0, *ls = xl0, *hd = xh1, *ld = xl1;
    for (int i = 0; i < 10; ++i) {
        const float* bs = (i < 7) ? exp_b + i * TWOD : ref_b + (i - 7) * TWOD;
        conv_mma_kernel<<<dim3(192, 4), 256, CONV_SMEM>>>(
            hs, ls, src, dst, hd, ld,
            wh + (size_t)i * TWOD * KTOT, wl + (size_t)i * TWOD * KTOT, bs, dils[i]);
        float* tf = src; src = dst; dst = tf;
        __nv_bfloat16* th = hs; hs = hd; hd = th;
        __nv_bfloat16* tl = ls; ls = ld; ld = tl;
    }
    // 10 swaps (even) -> final encodings in b0 == src
    sqnorm_kernel<<<NROWS, 32>>>(src);
    dist_rowmax_kernel<<<dim3(16, 16), 256>>>(src, am, tm);
    topk_ff_kernel<<<16, 256>>>(f1w, f1b, f2w, f2b, out);
}